// round 1
// baseline (speedup 1.0000x reference)
#include <cuda_runtime.h>
#include <math.h>

// Problem constants
static const int cB = 4;
static const int cS = 4096;
static const int cE = 2048;
static const int cH = 16;
#define HDIM 128
#define BQ 64
#define BKV 64

// Scratch (device globals -- no allocation allowed)
__device__ float g_xn[cB * cS * cE];                 // 134 MB  LN output
__device__ float g_qkv[cB * cS * 3 * cE];            // 402 MB  QKV (rope applied in place)
__device__ float g_attn[cB * cS * cE];               // 134 MB  attention output
__device__ float g_cos[cS * (HDIM / 2)];
__device__ float g_sin[cS * (HDIM / 2)];

// ---------------------------------------------------------------------------
// LayerNorm: one block per row (B*S rows), E=2048 floats per row.
// ---------------------------------------------------------------------------
__global__ __launch_bounds__(256) void ln_kernel(const float* __restrict__ x,
                                                 const float* __restrict__ w,
                                                 const float* __restrict__ b) {
    int row = blockIdx.x;
    int t = threadIdx.x;
    const float4* xr = (const float4*)(x + (size_t)row * cE);

    float4 v0 = xr[t];
    float4 v1 = xr[t + 256];

    float s = v0.x + v0.y + v0.z + v0.w + v1.x + v1.y + v1.z + v1.w;
    float ss = v0.x * v0.x + v0.y * v0.y + v0.z * v0.z + v0.w * v0.w +
               v1.x * v1.x + v1.y * v1.y + v1.z * v1.z + v1.w * v1.w;

    for (int off = 16; off; off >>= 1) {
        s  += __shfl_down_sync(0xffffffffu, s, off);
        ss += __shfl_down_sync(0xffffffffu, ss, off);
    }
    __shared__ float red0[8], red1[8];
    int warp = t >> 5, lane = t & 31;
    if (lane == 0) { red0[warp] = s; red1[warp] = ss; }
    __syncthreads();
    __shared__ float sMean, sRstd;
    if (t == 0) {
        float ts = 0.f, tss = 0.f;
        for (int i = 0; i < 8; i++) { ts += red0[i]; tss += red1[i]; }
        float mean = ts * (1.f / cE);
        float var = tss * (1.f / cE) - mean * mean;
        sMean = mean;
        sRstd = rsqrtf(var + 1e-5f);
    }
    __syncthreads();
    float mean = sMean, rstd = sRstd;

    float4* yr = (float4*)(g_xn + (size_t)row * cE);
    const float4* wr = (const float4*)w;
    const float4* br = (const float4*)b;

    float4 wv = wr[t], bv = br[t];
    float4 o;
    o.x = (v0.x - mean) * rstd * wv.x + bv.x;
    o.y = (v0.y - mean) * rstd * wv.y + bv.y;
    o.z = (v0.z - mean) * rstd * wv.z + bv.z;
    o.w = (v0.w - mean) * rstd * wv.w + bv.w;
    yr[t] = o;

    wv = wr[t + 256]; bv = br[t + 256];
    o.x = (v1.x - mean) * rstd * wv.x + bv.x;
    o.y = (v1.y - mean) * rstd * wv.y + bv.y;
    o.z = (v1.z - mean) * rstd * wv.z + bv.z;
    o.w = (v1.w - mean) * rstd * wv.w + bv.w;
    yr[t + 256] = o;
}

// ---------------------------------------------------------------------------
// RoPE angles: ang[s][f] = sum_d freqs[f][d] * pos[s][d], cos/sin tables.
// ---------------------------------------------------------------------------
__global__ void ang_kernel(const float* __restrict__ freqs,
                           const float* __restrict__ pos) {
    int s = blockIdx.x;
    int f = threadIdx.x;  // 0..63
    float a = freqs[f * 3 + 0] * pos[s * 3 + 0] +
              freqs[f * 3 + 1] * pos[s * 3 + 1] +
              freqs[f * 3 + 2] * pos[s * 3 + 2];
    g_cos[s * 64 + f] = cosf(a);
    g_sin[s * 64 + f] = sinf(a);
}

// ---------------------------------------------------------------------------
// RoPE applied in place to q and k parts of g_qkv.
// gid covers 2 * B*S*H*64 rotation pairs (part 0 = q, part 1 = k).
// ---------------------------------------------------------------------------
__global__ __launch_bounds__(256) void rope_kernel() {
    int gid = blockIdx.x * 256 + threadIdx.x;
    const int N = cB * cS * cH * 64;  // 2^24
    int part = (gid >= N) ? 1 : 0;
    int r = gid - part * N;
    int f = r & 63;
    int h = (r >> 6) & 15;
    int s = (r >> 10) & 4095;
    int b = r >> 22;
    float c = g_cos[s * 64 + f];
    float sn = g_sin[s * 64 + f];
    float2* p = (float2*)(g_qkv + ((size_t)(b * cS + s)) * (3 * cE) +
                          part * cE + h * HDIM + 2 * f);
    float2 t = *p;
    float2 o;
    o.x = t.x * c - t.y * sn;
    o.y = t.x * sn + t.y * c;
    *p = o;
}

// ---------------------------------------------------------------------------
// NT SGEMM: C[M,N] = A[M,K] @ W[N,K]^T + bias[N].
// 128x128 tile, BK=16, 256 threads, 8x8 per thread.
// ---------------------------------------------------------------------------
__global__ __launch_bounds__(256) void gemm_nt(const float* __restrict__ A,
                                               const float* __restrict__ W,
                                               const float* __restrict__ bias,
                                               float* __restrict__ C,
                                               int M, int N, int K) {
    __shared__ float As[16][132];
    __shared__ float Ws[16][132];

    int tid = threadIdx.x;
    int bm = blockIdx.y * 128;
    int bn = blockIdx.x * 128;
    int ty = tid >> 4, tx = tid & 15;

    const float* Ab = A + (size_t)bm * K;
    const float* Wb = W + (size_t)bn * K;

    float acc[8][8];
#pragma unroll
    for (int r = 0; r < 8; r++)
#pragma unroll
        for (int c = 0; c < 8; c++) acc[r][c] = 0.f;

    for (int k0 = 0; k0 < K; k0 += 16) {
#pragma unroll
        for (int i = 0; i < 2; i++) {
            int f = tid + i * 256;     // 0..511
            int row = f >> 2;          // 0..127
            int kq = f & 3;            // 0..3
            float4 av = *(const float4*)(Ab + (size_t)row * K + k0 + kq * 4);
            float4 wv = *(const float4*)(Wb + (size_t)row * K + k0 + kq * 4);
            int kk = kq * 4;
            As[kk + 0][row] = av.x; As[kk + 1][row] = av.y;
            As[kk + 2][row] = av.z; As[kk + 3][row] = av.w;
            Ws[kk + 0][row] = wv.x; Ws[kk + 1][row] = wv.y;
            Ws[kk + 2][row] = wv.z; Ws[kk + 3][row] = wv.w;
        }
        __syncthreads();
#pragma unroll
        for (int k = 0; k < 16; k++) {
            float a[8], w[8];
            *(float4*)(a)     = *(float4*)&As[k][ty * 8];
            *(float4*)(a + 4) = *(float4*)&As[k][ty * 8 + 4];
            *(float4*)(w)     = *(float4*)&Ws[k][tx * 8];
            *(float4*)(w + 4) = *(float4*)&Ws[k][tx * 8 + 4];
#pragma unroll
            for (int r = 0; r < 8; r++)
#pragma unroll
                for (int c = 0; c < 8; c++) acc[r][c] += a[r] * w[c];
        }
        __syncthreads();
    }

#pragma unroll
    for (int r = 0; r < 8; r++) {
        float* crow = C + (size_t)(bm + ty * 8 + r) * N + bn + tx * 8;
        float4 o0, o1;
        o0.x = acc[r][0] + bias[bn + tx * 8 + 0];
        o0.y = acc[r][1] + bias[bn + tx * 8 + 1];
        o0.z = acc[r][2] + bias[bn + tx * 8 + 2];
        o0.w = acc[r][3] + bias[bn + tx * 8 + 3];
        o1.x = acc[r][4] + bias[bn + tx * 8 + 4];
        o1.y = acc[r][5] + bias[bn + tx * 8 + 5];
        o1.z = acc[r][6] + bias[bn + tx * 8 + 6];
        o1.w = acc[r][7] + bias[bn + tx * 8 + 7];
        *(float4*)(crow)     = o0;
        *(float4*)(crow + 4) = o1;
    }
}

// ---------------------------------------------------------------------------
// Flash attention (non-causal, full softmax): grid (S/BQ, B*H), 256 threads.
// Q/K stored d-major (transposed) in smem, V row-major; online softmax.
// ---------------------------------------------------------------------------
__global__ __launch_bounds__(256) void flash_kernel() {
    extern __shared__ float sm[];
    float* Qs = sm;                   // [HDIM][68]
    float* Ks = Qs + HDIM * 68;       // [HDIM][68]
    float* Vs = Ks + HDIM * 68;       // [BKV][132]
    float* Ps = Vs + BKV * 132;       // [BQ][68]
    float* mrow = Ps + BQ * 68;       // [64]
    float* lrow = mrow + 64;          // [64]
    float* arow = lrow + 64;          // [64]

    int tid = threadIdx.x;
    int qt = blockIdx.x;
    int bh = blockIdx.y;
    int b = bh >> 4, h = bh & 15;
    const int rs = 3 * cE;
    const float* qb = g_qkv + ((size_t)b * cS) * rs + h * HDIM;
    const float* kb = qb + cE;
    const float* vb = qb + 2 * cE;
    int s0 = qt * BQ;
    const float scale = 0.088388347648318440550f;  // 1/sqrt(128)

    // Load Q tile transposed, scale baked in.
#pragma unroll
    for (int it = 0; it < 8; it++) {
        int f = tid + it * 256;  // 0..2047
        int i = f >> 5;          // 0..63
        int dq = f & 31;         // float4 index along d
        float4 v = *(const float4*)(qb + (size_t)(s0 + i) * rs + dq * 4);
        int d = dq * 4;
        Qs[(d + 0) * 68 + i] = v.x * scale;
        Qs[(d + 1) * 68 + i] = v.y * scale;
        Qs[(d + 2) * 68 + i] = v.z * scale;
        Qs[(d + 3) * 68 + i] = v.w * scale;
    }
    if (tid < 64) { mrow[tid] = -INFINITY; lrow[tid] = 0.f; }

    float o[4][8];
#pragma unroll
    for (int r = 0; r < 4; r++)
#pragma unroll
        for (int c = 0; c < 8; c++) o[r][c] = 0.f;

    int ti = tid >> 4, tj = tid & 15;
    int r4 = tid >> 2, q4 = tid & 3;

    for (int kt = 0; kt < cS / BKV; kt++) {
        __syncthreads();  // protect Ks/Vs/Ps from previous iteration readers
#pragma unroll
        for (int it = 0; it < 8; it++) {
            int f = tid + it * 256;
            int j = f >> 5;
            int dq = f & 31;
            size_t goff = (size_t)(kt * BKV + j) * rs + dq * 4;
            float4 kv = *(const float4*)(kb + goff);
            float4 vv = *(const float4*)(vb + goff);
            int d = dq * 4;
            Ks[(d + 0) * 68 + j] = kv.x;
            Ks[(d + 1) * 68 + j] = kv.y;
            Ks[(d + 2) * 68 + j] = kv.z;
            Ks[(d + 3) * 68 + j] = kv.w;
            *(float4*)&Vs[j * 132 + d] = vv;
        }
        __syncthreads();

        // S = (Q*scale) K^T   (each thread 4x4)
        float sacc[4][4];
#pragma unroll
        for (int r = 0; r < 4; r++)
#pragma unroll
            for (int c = 0; c < 4; c++) sacc[r][c] = 0.f;

#pragma unroll 4
        for (int d = 0; d < HDIM; d++) {
            float4 qv = *(float4*)&Qs[d * 68 + ti * 4];
            float4 kv = *(float4*)&Ks[d * 68 + tj * 4];
            float qa[4] = {qv.x, qv.y, qv.z, qv.w};
            float ka[4] = {kv.x, kv.y, kv.z, kv.w};
#pragma unroll
            for (int r = 0; r < 4; r++)
#pragma unroll
                for (int c = 0; c < 4; c++) sacc[r][c] += qa[r] * ka[c];
        }
#pragma unroll
        for (int r = 0; r < 4; r++)
#pragma unroll
            for (int c = 0; c < 4; c++)
                Ps[(ti * 4 + r) * 68 + tj * 4 + c] = sacc[r][c];
        __syncthreads();

        // Online softmax: 4 threads per row, 16 cols each.
        {
            float vals[16];
            float mx = -INFINITY;
            int base = r4 * 68 + q4 * 16;
#pragma unroll
            for (int j = 0; j < 16; j++) {
                vals[j] = Ps[base + j];
                mx = fmaxf(mx, vals[j]);
            }
            mx = fmaxf(mx, __shfl_xor_sync(0xffffffffu, mx, 1));
            mx = fmaxf(mx, __shfl_xor_sync(0xffffffffu, mx, 2));
            float mold = mrow[r4];
            float mnew = fmaxf(mold, mx);
            float sum = 0.f;
#pragma unroll
            for (int j = 0; j < 16; j++) {
                float e = __expf(vals[j] - mnew);
                Ps[base + j] = e;
                sum += e;
            }
            sum += __shfl_xor_sync(0xffffffffu, sum, 1);
            sum += __shfl_xor_sync(0xffffffffu, sum, 2);
            if (q4 == 0) {
                float al = __expf(mold - mnew);
                arow[r4] = al;
                mrow[r4] = mnew;
                lrow[r4] = lrow[r4] * al + sum;
            }
        }
        __syncthreads();

        // O = O*alpha + P @ V   (each thread 4 rows x 8 cols of O)
        float al[4];
#pragma unroll
        for (int r = 0; r < 4; r++) al[r] = arow[ti * 4 + r];
#pragma unroll
        for (int r = 0; r < 4; r++)
#pragma unroll
            for (int c = 0; c < 8; c++) o[r][c] *= al[r];

#pragma unroll 2
        for (int j = 0; j < BKV; j++) {
            float p[4];
#pragma unroll
            for (int r = 0; r < 4; r++) p[r] = Ps[(ti * 4 + r) * 68 + j];
            float4 v0 = *(float4*)&Vs[j * 132 + tj * 8];
            float4 v1 = *(float4*)&Vs[j * 132 + tj * 8 + 4];
            float va[8] = {v0.x, v0.y, v0.z, v0.w, v1.x, v1.y, v1.z, v1.w};
#pragma unroll
            for (int r = 0; r < 4; r++)
#pragma unroll
                for (int c = 0; c < 8; c++) o[r][c] += p[r] * va[c];
        }
    }

    float linv[4];
#pragma unroll
    for (int r = 0; r < 4; r++) linv[r] = 1.f / lrow[ti * 4 + r];

    float* ob = g_attn + ((size_t)b * cS + s0) * cE + h * HDIM;
#pragma unroll
    for (int r = 0; r < 4; r++) {
        float4 w0, w1;
        w0.x = o[r][0] * linv[r]; w0.y = o[r][1] * linv[r];
        w0.z = o[r][2] * linv[r]; w0.w = o[r][3] * linv[r];
        w1.x = o[r][4] * linv[r]; w1.y = o[r][5] * linv[r];
        w1.z = o[r][6] * linv[r]; w1.w = o[r][7] * linv[r];
        *(float4*)(ob + (size_t)(ti * 4 + r) * cE + tj * 8)     = w0;
        *(float4*)(ob + (size_t)(ti * 4 + r) * cE + tj * 8 + 4) = w1;
    }
}

// ---------------------------------------------------------------------------
// Launch
// ---------------------------------------------------------------------------
extern "C" void kernel_launch(void* const* d_in, const int* in_sizes, int n_in,
                              void* d_out, int out_size) {
    const float* x        = (const float*)d_in[0];
    const float* position = (const float*)d_in[1];
    const float* ln_w     = (const float*)d_in[2];
    const float* ln_b     = (const float*)d_in[3];
    const float* qkv_w    = (const float*)d_in[4];
    const float* qkv_b    = (const float*)d_in[5];
    const float* out_w    = (const float*)d_in[6];
    const float* out_b    = (const float*)d_in[7];
    const float* freqs    = (const float*)d_in[8];
    float* out = (float*)d_out;

    float *pxn, *pqkv, *pattn;
    cudaGetSymbolAddress((void**)&pxn, g_xn);
    cudaGetSymbolAddress((void**)&pqkv, g_qkv);
    cudaGetSymbolAddress((void**)&pattn, g_attn);

    const int SMEM_FA = (HDIM * 68 * 2 + BKV * 132 + BQ * 68 + 192) * 4;  // 121600 B
    cudaFuncSetAttribute(flash_kernel, cudaFuncAttributeMaxDynamicSharedMemorySize,
                         SMEM_FA);

    // 1. LayerNorm
    ln_kernel<<<cB * cS, 256>>>(x, ln_w, ln_b);

    // 2. RoPE angle tables
    ang_kernel<<<cS, 64>>>(freqs, position);

    // 3. QKV projection: [16384,2048] @ [6144,2048]^T
    gemm_nt<<<dim3(3 * cE / 128, cB * cS / 128), 256>>>(
        pxn, qkv_w, qkv_b, pqkv, cB * cS, 3 * cE, cE);

    // 4. RoPE on q and k (in place)
    rope_kernel<<<(2 * cB * cS * cH * 64) / 256, 256>>>();

    // 5. Flash attention
    flash_kernel<<<dim3(cS / BQ, cB * cH), 256, SMEM_FA>>>();

    // 6. Output projection: [16384,2048] @ [2048,2048]^T -> d_out
    gemm_nt<<<dim3(cE / 128, cB * cS / 128), 256>>>(
        pattn, out_w, out_b, out, cB * cS, cE, cE);
}

// round 3
// speedup vs baseline: 1.2626x; 1.2626x over previous
#include <cuda_runtime.h>
#include <cuda_bf16.h>
#include <cstdint>
#include <math.h>

// Problem constants
static const int cB = 4;
static const int cS = 4096;
static const int cE = 2048;
static const int cH = 16;
#define HDIM 128
#define BQ 64
#define BKV 64

// ---------------------------------------------------------------------------
// Helpers
// ---------------------------------------------------------------------------
__device__ __forceinline__ uint32_t smem_u32(const void* p) {
    uint32_t a;
    asm("{ .reg .u64 t; cvta.to.shared.u64 t, %1; cvt.u32.u64 %0, t; }"
        : "=r"(a) : "l"(p));
    return a;
}
__device__ __forceinline__ void cp16(uint32_t dst, const void* src) {
    asm volatile("cp.async.cg.shared.global [%0], [%1], 16;" :: "r"(dst), "l"(src));
}
#define CP_COMMIT() asm volatile("cp.async.commit_group;" ::: "memory")
#define CP_WAIT(n)  asm volatile("cp.async.wait_group %0;" :: "n"(n) : "memory")
#define LDSM4(d, addr)                                                        \
    asm volatile("ldmatrix.sync.aligned.m8n8.x4.shared.b16 {%0,%1,%2,%3}, [%4];" \
                 : "=r"((d)[0]), "=r"((d)[1]), "=r"((d)[2]), "=r"((d)[3])     \
                 : "r"(addr))
__device__ __forceinline__ void mma16816(float* c, const uint32_t* a,
                                         const uint32_t* b) {
    asm volatile(
        "mma.sync.aligned.m16n8k16.row.col.f32.bf16.bf16.f32 "
        "{%0,%1,%2,%3}, {%4,%5,%6,%7}, {%8,%9}, {%0,%1,%2,%3};"
        : "+f"(c[0]), "+f"(c[1]), "+f"(c[2]), "+f"(c[3])
        : "r"(a[0]), "r"(a[1]), "r"(a[2]), "r"(a[3]), "r"(b[0]), "r"(b[1]));
}

// ---------------------------------------------------------------------------
// Scratch (device globals)
// ---------------------------------------------------------------------------
__device__ __align__(256) float g_qkv[cB * cS * 3 * cE];          // 402 MB
__device__ __align__(256) float g_attn[cB * cS * cE];             // 134 MB
__device__ __align__(256) __nv_bfloat16 g_xnh[cB * cS * cE];
__device__ __align__(256) __nv_bfloat16 g_xnl[cB * cS * cE];
__device__ __align__(256) __nv_bfloat16 g_qwh[3 * cE * cE];
__device__ __align__(256) __nv_bfloat16 g_qwl[3 * cE * cE];
__device__ __align__(256) __nv_bfloat16 g_owh[cE * cE];
__device__ __align__(256) __nv_bfloat16 g_owl[cE * cE];
__device__ __align__(256) __nv_bfloat16 g_ah[cB * cS * cE];
__device__ __align__(256) __nv_bfloat16 g_al[cB * cS * cE];
__device__ float g_cos[cS * (HDIM / 2)];
__device__ float g_sin[cS * (HDIM / 2)];

__device__ __forceinline__ uint32_t pack_bf2(float a, float b) {
    __nv_bfloat162 t;
    t.x = __float2bfloat16_rn(a);
    t.y = __float2bfloat16_rn(b);
    return *(uint32_t*)&t;
}

// ---------------------------------------------------------------------------
// LayerNorm -> bf16 hi/lo split output
// ---------------------------------------------------------------------------
__global__ __launch_bounds__(256) void ln_split_kernel(const float* __restrict__ x,
                                                       const float* __restrict__ w,
                                                       const float* __restrict__ b) {
    int row = blockIdx.x;
    int t = threadIdx.x;
    const float4* xr = (const float4*)(x + (size_t)row * cE);

    float4 v0 = xr[t];
    float4 v1 = xr[t + 256];

    float s = v0.x + v0.y + v0.z + v0.w + v1.x + v1.y + v1.z + v1.w;
    float ss = v0.x * v0.x + v0.y * v0.y + v0.z * v0.z + v0.w * v0.w +
               v1.x * v1.x + v1.y * v1.y + v1.z * v1.z + v1.w * v1.w;

    for (int off = 16; off; off >>= 1) {
        s  += __shfl_down_sync(0xffffffffu, s, off);
        ss += __shfl_down_sync(0xffffffffu, ss, off);
    }
    __shared__ float red0[8], red1[8];
    int warp = t >> 5, lane = t & 31;
    if (lane == 0) { red0[warp] = s; red1[warp] = ss; }
    __syncthreads();
    __shared__ float sMean, sRstd;
    if (t == 0) {
        float ts = 0.f, tss = 0.f;
        for (int i = 0; i < 8; i++) { ts += red0[i]; tss += red1[i]; }
        float mean = ts * (1.f / cE);
        float var = tss * (1.f / cE) - mean * mean;
        sMean = mean;
        sRstd = rsqrtf(var + 1e-5f);
    }
    __syncthreads();
    float mean = sMean, rstd = sRstd;

    const float4* wr = (const float4*)w;
    const float4* br = (const float4*)b;
    uint2* hr = (uint2*)(g_xnh + (size_t)row * cE);
    uint2* lr = (uint2*)(g_xnl + (size_t)row * cE);

#pragma unroll
    for (int half = 0; half < 2; half++) {
        int idx = t + half * 256;
        float4 v = half ? v1 : v0;
        float4 wv = wr[idx], bv = br[idx];
        float o0 = (v.x - mean) * rstd * wv.x + bv.x;
        float o1 = (v.y - mean) * rstd * wv.y + bv.y;
        float o2 = (v.z - mean) * rstd * wv.z + bv.z;
        float o3 = (v.w - mean) * rstd * wv.w + bv.w;
        __nv_bfloat16 h0 = __float2bfloat16_rn(o0);
        __nv_bfloat16 h1 = __float2bfloat16_rn(o1);
        __nv_bfloat16 h2 = __float2bfloat16_rn(o2);
        __nv_bfloat16 h3 = __float2bfloat16_rn(o3);
        uint2 hv, lv;
        {
            __nv_bfloat162 p01; p01.x = h0; p01.y = h1;
            __nv_bfloat162 p23; p23.x = h2; p23.y = h3;
            hv.x = *(uint32_t*)&p01; hv.y = *(uint32_t*)&p23;
        }
        lv.x = pack_bf2(o0 - __bfloat162float(h0), o1 - __bfloat162float(h1));
        lv.y = pack_bf2(o2 - __bfloat162float(h2), o3 - __bfloat162float(h3));
        hr[idx] = hv;
        lr[idx] = lv;
    }
}

// ---------------------------------------------------------------------------
// fp32 -> bf16 hi/lo split
// ---------------------------------------------------------------------------
__global__ __launch_bounds__(256) void split_kernel(const float* __restrict__ src,
                                                    __nv_bfloat16* __restrict__ hi,
                                                    __nv_bfloat16* __restrict__ lo,
                                                    int n4) {
    int i = blockIdx.x * 256 + threadIdx.x;
    if (i >= n4) return;
    float4 v = ((const float4*)src)[i];
    __nv_bfloat16 h0 = __float2bfloat16_rn(v.x);
    __nv_bfloat16 h1 = __float2bfloat16_rn(v.y);
    __nv_bfloat16 h2 = __float2bfloat16_rn(v.z);
    __nv_bfloat16 h3 = __float2bfloat16_rn(v.w);
    uint2 hv, lv;
    {
        __nv_bfloat162 p01; p01.x = h0; p01.y = h1;
        __nv_bfloat162 p23; p23.x = h2; p23.y = h3;
        hv.x = *(uint32_t*)&p01; hv.y = *(uint32_t*)&p23;
    }
    lv.x = pack_bf2(v.x - __bfloat162float(h0), v.y - __bfloat162float(h1));
    lv.y = pack_bf2(v.z - __bfloat162float(h2), v.w - __bfloat162float(h3));
    ((uint2*)hi)[i] = hv;
    ((uint2*)lo)[i] = lv;
}

// ---------------------------------------------------------------------------
// RoPE angles
// ---------------------------------------------------------------------------
__global__ void ang_kernel(const float* __restrict__ freqs,
                           const float* __restrict__ pos) {
    int s = blockIdx.x;
    int f = threadIdx.x;  // 0..63
    float a = freqs[f * 3 + 0] * pos[s * 3 + 0] +
              freqs[f * 3 + 1] * pos[s * 3 + 1] +
              freqs[f * 3 + 2] * pos[s * 3 + 2];
    g_cos[s * 64 + f] = cosf(a);
    g_sin[s * 64 + f] = sinf(a);
}

// ---------------------------------------------------------------------------
// RoPE in place on q,k of g_qkv
// ---------------------------------------------------------------------------
__global__ __launch_bounds__(256) void rope_kernel() {
    int gid = blockIdx.x * 256 + threadIdx.x;
    const int N = cB * cS * cH * 64;
    int part = (gid >= N) ? 1 : 0;
    int r = gid - part * N;
    int f = r & 63;
    int h = (r >> 6) & 15;
    int s = (r >> 10) & 4095;
    int b = r >> 22;
    float c = g_cos[s * 64 + f];
    float sn = g_sin[s * 64 + f];
    float2* p = (float2*)(g_qkv + ((size_t)(b * cS + s)) * (3 * cE) +
                          part * cE + h * HDIM + 2 * f);
    float2 t = *p;
    float2 o;
    o.x = t.x * c - t.y * sn;
    o.y = t.x * sn + t.y * c;
    *p = o;
}

// ---------------------------------------------------------------------------
// HMMA bf16-split GEMM: C[M,N] = (Ah+Al)[M,K] @ (Wh+Wl)[N,K]^T + bias.
// 128x128x32 CTA tile, 8 warps (warp tile 64x32), mma.sync.m16n8k16,
// 3 MMAs per logical tile (AhWh + AhWl + AlWh). Double-buffered cp.async.
// Tile rows padded: 32 bf16 data + 8 pad = 72 bf16 = 144 B (stride%128==16
// -> ldmatrix phases conflict-free).
// ---------------------------------------------------------------------------
#define GBK 32
#define TSTRIDE 72                       // bf16 per smem row
#define TROWB (TSTRIDE * 2)              // 144 B
#define TILE_B (128 * TROWB)             // 18432 B per tile
#define GEMM_SMEM (2 * 4 * TILE_B)       // 147456 B

__global__ __launch_bounds__(256, 1) void gemm_bf3(
    const __nv_bfloat16* __restrict__ Ah, const __nv_bfloat16* __restrict__ Al,
    const __nv_bfloat16* __restrict__ Wh, const __nv_bfloat16* __restrict__ Wl,
    const float* __restrict__ bias, float* __restrict__ C, int N, int K) {
    extern __shared__ __align__(128) char smem[];
    uint32_t sb = smem_u32(smem);
    int tid = threadIdx.x;
    int wid = tid >> 5, lane = tid & 31;
    int bm = blockIdx.y * 128, bn = blockIdx.x * 128;
    int wm = wid & 1, wn = wid >> 1;  // warp tile origin (wm*64, wn*32)

    const __nv_bfloat16* s0 = Ah + (size_t)bm * K;
    const __nv_bfloat16* s1 = Al + (size_t)bm * K;
    const __nv_bfloat16* s2 = Wh + (size_t)bn * K;
    const __nv_bfloat16* s3 = Wl + (size_t)bn * K;

    auto load = [&](int buf, int k0) {
        uint32_t base = sb + (uint32_t)buf * (4 * TILE_B);
#pragma unroll
        for (int i = 0; i < 2; i++) {
            int idx = tid + i * 256;            // 0..511
            int row = idx >> 2, c = idx & 3;
            uint32_t so = (uint32_t)row * TROWB + c * 16;
            size_t go = (size_t)row * K + k0 + c * 8;
            cp16(base + 0 * TILE_B + so, s0 + go);
            cp16(base + 1 * TILE_B + so, s1 + go);
            cp16(base + 2 * TILE_B + so, s2 + go);
            cp16(base + 3 * TILE_B + so, s3 + go);
        }
        CP_COMMIT();
    };

    float acc[4][4][4];
#pragma unroll
    for (int mf = 0; mf < 4; mf++)
#pragma unroll
        for (int nf = 0; nf < 4; nf++)
#pragma unroll
            for (int e = 0; e < 4; e++) acc[mf][nf][e] = 0.f;

    int g = lane >> 3, r = lane & 7;
    // ldmatrix per-lane address pieces
    uint32_t a_row = (uint32_t)(r + (g & 1) * 8) * TROWB + (uint32_t)(g >> 1) * 16;
    uint32_t b_row = (uint32_t)(r + (g >> 1) * 8) * TROWB + (uint32_t)(g & 1) * 16;

    load(0, 0);
    int nCh = K / GBK;
    for (int ic = 0; ic < nCh; ic++) {
        int buf = ic & 1;
        if (ic + 1 < nCh) {
            load(buf ^ 1, (ic + 1) * GBK);
            CP_WAIT(1);
        } else {
            CP_WAIT(0);
        }
        __syncthreads();

        uint32_t base = sb + (uint32_t)buf * (4 * TILE_B);
        uint32_t aH = base + 0 * TILE_B + (uint32_t)(wm * 64) * TROWB + a_row;
        uint32_t aL = base + 1 * TILE_B + (uint32_t)(wm * 64) * TROWB + a_row;
        uint32_t bH = base + 2 * TILE_B + (uint32_t)(wn * 32) * TROWB + b_row;
        uint32_t bL = base + 3 * TILE_B + (uint32_t)(wn * 32) * TROWB + b_row;

#pragma unroll
        for (int kk = 0; kk < GBK; kk += 16) {
            uint32_t ah[4][4], al[4][4];
#pragma unroll
            for (int mf = 0; mf < 4; mf++) {
                LDSM4(ah[mf], aH + (uint32_t)(mf * 16) * TROWB + kk * 2);
                LDSM4(al[mf], aL + (uint32_t)(mf * 16) * TROWB + kk * 2);
            }
            uint32_t bh[2][4], bl[2][4];
#pragma unroll
            for (int nb = 0; nb < 2; nb++) {
                LDSM4(bh[nb], bH + (uint32_t)(nb * 16) * TROWB + kk * 2);
                LDSM4(bl[nb], bL + (uint32_t)(nb * 16) * TROWB + kk * 2);
            }
#pragma unroll
            for (int mf = 0; mf < 4; mf++) {
#pragma unroll
                for (int nf = 0; nf < 4; nf++) {
                    uint32_t* ph = &bh[nf >> 1][(nf & 1) * 2];
                    uint32_t* pl = &bl[nf >> 1][(nf & 1) * 2];
                    mma16816(acc[mf][nf], ah[mf], ph);
                    mma16816(acc[mf][nf], ah[mf], pl);
                    mma16816(acc[mf][nf], al[mf], ph);
                }
            }
        }
        __syncthreads();
    }

    // Epilogue: direct global write with bias.
    int gq = lane >> 2, tc = lane & 3;
#pragma unroll
    for (int mf = 0; mf < 4; mf++) {
        int row0 = bm + wm * 64 + mf * 16 + gq;
#pragma unroll
        for (int nf = 0; nf < 4; nf++) {
            int col = bn + wn * 32 + nf * 8 + tc * 2;
            float b0 = bias[col], b1 = bias[col + 1];
            float2 v0, v1;
            v0.x = acc[mf][nf][0] + b0;
            v0.y = acc[mf][nf][1] + b1;
            v1.x = acc[mf][nf][2] + b0;
            v1.y = acc[mf][nf][3] + b1;
            *(float2*)(C + (size_t)row0 * N + col) = v0;
            *(float2*)(C + (size_t)(row0 + 8) * N + col) = v1;
        }
    }
}

// ---------------------------------------------------------------------------
// Flash attention (fp32 SIMT)
// ---------------------------------------------------------------------------
__global__ __launch_bounds__(256) void flash_kernel() {
    extern __shared__ float sm[];
    float* Qs = sm;                   // [HDIM][68]
    float* Ks = Qs + HDIM * 68;       // [HDIM][68]
    float* Vs = Ks + HDIM * 68;       // [BKV][132]
    float* Ps = Vs + BKV * 132;       // [BQ][68]
    float* mrow = Ps + BQ * 68;
    float* lrow = mrow + 64;
    float* arow = lrow + 64;

    int tid = threadIdx.x;
    int qt = blockIdx.x;
    int bh = blockIdx.y;
    int b = bh >> 4, h = bh & 15;
    const int rs = 3 * cE;
    const float* qb = g_qkv + ((size_t)b * cS) * rs + h * HDIM;
    const float* kb = qb + cE;
    const float* vb = qb + 2 * cE;
    int s0 = qt * BQ;
    const float scale = 0.088388347648318440550f;

#pragma unroll
    for (int it = 0; it < 8; it++) {
        int f = tid + it * 256;
        int i = f >> 5;
        int dq = f & 31;
        float4 v = *(const float4*)(qb + (size_t)(s0 + i) * rs + dq * 4);
        int d = dq * 4;
        Qs[(d + 0) * 68 + i] = v.x * scale;
        Qs[(d + 1) * 68 + i] = v.y * scale;
        Qs[(d + 2) * 68 + i] = v.z * scale;
        Qs[(d + 3) * 68 + i] = v.w * scale;
    }
    if (tid < 64) { mrow[tid] = -INFINITY; lrow[tid] = 0.f; }

    float o[4][8];
#pragma unroll
    for (int r = 0; r < 4; r++)
#pragma unroll
        for (int c = 0; c < 8; c++) o[r][c] = 0.f;

    int ti = tid >> 4, tj = tid & 15;
    int r4 = tid >> 2, q4 = tid & 3;

    for (int kt = 0; kt < cS / BKV; kt++) {
        __syncthreads();
#pragma unroll
        for (int it = 0; it < 8; it++) {
            int f = tid + it * 256;
            int j = f >> 5;
            int dq = f & 31;
            size_t goff = (size_t)(kt * BKV + j) * rs + dq * 4;
            float4 kv = *(const float4*)(kb + goff);
            float4 vv = *(const float4*)(vb + goff);
            int d = dq * 4;
            Ks[(d + 0) * 68 + j] = kv.x;
            Ks[(d + 1) * 68 + j] = kv.y;
            Ks[(d + 2) * 68 + j] = kv.z;
            Ks[(d + 3) * 68 + j] = kv.w;
            *(float4*)&Vs[j * 132 + d] = vv;
        }
        __syncthreads();

        float sacc[4][4];
#pragma unroll
        for (int r = 0; r < 4; r++)
#pragma unroll
            for (int c = 0; c < 4; c++) sacc[r][c] = 0.f;

#pragma unroll 4
        for (int d = 0; d < HDIM; d++) {
            float4 qv = *(float4*)&Qs[d * 68 + ti * 4];
            float4 kv = *(float4*)&Ks[d * 68 + tj * 4];
            float qa[4] = {qv.x, qv.y, qv.z, qv.w};
            float ka[4] = {kv.x, kv.y, kv.z, kv.w};
#pragma unroll
            for (int r = 0; r < 4; r++)
#pragma unroll
                for (int c = 0; c < 4; c++) sacc[r][c] += qa[r] * ka[c];
        }
#pragma unroll
        for (int r = 0; r < 4; r++)
#pragma unroll
            for (int c = 0; c < 4; c++)
                Ps[(ti * 4 + r) * 68 + tj * 4 + c] = sacc[r][c];
        __syncthreads();

        {
            float vals[16];
            float mx = -INFINITY;
            int base = r4 * 68 + q4 * 16;
#pragma unroll
            for (int j = 0; j < 16; j++) {
                vals[j] = Ps[base + j];
                mx = fmaxf(mx, vals[j]);
            }
            mx = fmaxf(mx, __shfl_xor_sync(0xffffffffu, mx, 1));
            mx = fmaxf(mx, __shfl_xor_sync(0xffffffffu, mx, 2));
            float mold = mrow[r4];
            float mnew = fmaxf(mold, mx);
            float sum = 0.f;
#pragma unroll
            for (int j = 0; j < 16; j++) {
                float e = __expf(vals[j] - mnew);
                Ps[base + j] = e;
                sum += e;
            }
            sum += __shfl_xor_sync(0xffffffffu, sum, 1);
            sum += __shfl_xor_sync(0xffffffffu, sum, 2);
            if (q4 == 0) {
                float al = __expf(mold - mnew);
                arow[r4] = al;
                mrow[r4] = mnew;
                lrow[r4] = lrow[r4] * al + sum;
            }
        }
        __syncthreads();

        float al[4];
#pragma unroll
        for (int r = 0; r < 4; r++) al[r] = arow[ti * 4 + r];
#pragma unroll
        for (int r = 0; r < 4; r++)
#pragma unroll
            for (int c = 0; c < 8; c++) o[r][c] *= al[r];

#pragma unroll 2
        for (int j = 0; j < BKV; j++) {
            float p[4];
#pragma unroll
            for (int r = 0; r < 4; r++) p[r] = Ps[(ti * 4 + r) * 68 + j];
            float4 v0 = *(float4*)&Vs[j * 132 + tj * 8];
            float4 v1 = *(float4*)&Vs[j * 132 + tj * 8 + 4];
            float va[8] = {v0.x, v0.y, v0.z, v0.w, v1.x, v1.y, v1.z, v1.w};
#pragma unroll
            for (int r = 0; r < 4; r++)
#pragma unroll
                for (int c = 0; c < 8; c++) o[r][c] += p[r] * va[c];
        }
    }

    float linv[4];
#pragma unroll
    for (int r = 0; r < 4; r++) linv[r] = 1.f / lrow[ti * 4 + r];

    float* ob = g_attn + ((size_t)b * cS + s0) * cE + h * HDIM;
#pragma unroll
    for (int r = 0; r < 4; r++) {
        float4 w0, w1;
        w0.x = o[r][0] * linv[r]; w0.y = o[r][1] * linv[r];
        w0.z = o[r][2] * linv[r]; w0.w = o[r][3] * linv[r];
        w1.x = o[r][4] * linv[r]; w1.y = o[r][5] * linv[r];
        w1.z = o[r][6] * linv[r]; w1.w = o[r][7] * linv[r];
        *(float4*)(ob + (size_t)(ti * 4 + r) * cE + tj * 8)     = w0;
        *(float4*)(ob + (size_t)(ti * 4 + r) * cE + tj * 8 + 4) = w1;
    }
}

// ---------------------------------------------------------------------------
// Launch
// ---------------------------------------------------------------------------
extern "C" void kernel_launch(void* const* d_in, const int* in_sizes, int n_in,
                              void* d_out, int out_size) {
    const float* x        = (const float*)d_in[0];
    const float* position = (const float*)d_in[1];
    const float* ln_w     = (const float*)d_in[2];
    const float* ln_b     = (const float*)d_in[3];
    const float* qkv_w    = (const float*)d_in[4];
    const float* qkv_b    = (const float*)d_in[5];
    const float* out_w    = (const float*)d_in[6];
    const float* out_b    = (const float*)d_in[7];
    const float* freqs    = (const float*)d_in[8];
    float* out = (float*)d_out;

    float *pqkv, *pattn;
    __nv_bfloat16 *pxnh, *pxnl, *pqwh, *pqwl, *powh, *powl, *pah, *pal;
    cudaGetSymbolAddress((void**)&pqkv, g_qkv);
    cudaGetSymbolAddress((void**)&pattn, g_attn);
    cudaGetSymbolAddress((void**)&pxnh, g_xnh);
    cudaGetSymbolAddress((void**)&pxnl, g_xnl);
    cudaGetSymbolAddress((void**)&pqwh, g_qwh);
    cudaGetSymbolAddress((void**)&pqwl, g_qwl);
    cudaGetSymbolAddress((void**)&powh, g_owh);
    cudaGetSymbolAddress((void**)&powl, g_owl);
    cudaGetSymbolAddress((void**)&pah, g_ah);
    cudaGetSymbolAddress((void**)&pal, g_al);

    const int SMEM_FA = (HDIM * 68 * 2 + BKV * 132 + BQ * 68 + 192) * 4;
    cudaFuncSetAttribute(flash_kernel, cudaFuncAttributeMaxDynamicSharedMemorySize,
                         SMEM_FA);
    cudaFuncSetAttribute(gemm_bf3, cudaFuncAttributeMaxDynamicSharedMemorySize,
                         GEMM_SMEM);

    // 1. LayerNorm -> bf16 hi/lo
    ln_split_kernel<<<cB * cS, 256>>>(x, ln_w, ln_b);

    // 2. RoPE angle tables
    ang_kernel<<<cS, 64>>>(freqs, position);

    // 3. Split QKV weights
    split_kernel<<<(3 * cE * cE / 4 + 255) / 256, 256>>>(qkv_w, pqwh, pqwl,
                                                         3 * cE * cE / 4);

    // 4. QKV projection (HMMA): [16384,2048] @ [6144,2048]^T
    gemm_bf3<<<dim3(3 * cE / 128, cB * cS / 128), 256, GEMM_SMEM>>>(
        pxnh, pxnl, pqwh, pqwl, qkv_b, pqkv, 3 * cE, cE);

    // 5. RoPE on q,k
    rope_kernel<<<(2 * cB * cS * cH * 64) / 256, 256>>>();

    // 6. Flash attention (fp32 SIMT)
    flash_kernel<<<dim3(cS / BQ, cB * cH), 256, SMEM_FA>>>();

    // 7. Split attention output + out weights
    split_kernel<<<(cB * cS * cE / 4 + 255) / 256, 256>>>(pattn, pah, pal,
                                                          cB * cS * cE / 4);
    split_kernel<<<(cE * cE / 4 + 255) / 256, 256>>>(out_w, powh, powl,
                                                     cE * cE / 4);

    // 8. Output projection (HMMA) -> d_out
    gemm_bf3<<<dim3(cE / 128, cB * cS / 128), 256, GEMM_SMEM>>>(
        pah, pal, powh, powl, out_b, out, cE, cE);
}

// round 4
// speedup vs baseline: 3.9462x; 3.1256x over previous
#include <cuda_runtime.h>
#include <cuda_bf16.h>
#include <cuda_fp16.h>
#include <cstdint>
#include <math.h>

// Problem constants
static const int cB = 4;
static const int cS = 4096;
static const int cE = 2048;
static const int cH = 16;
#define HDIM 128

// ---------------------------------------------------------------------------
// Helpers
// ---------------------------------------------------------------------------
__device__ __forceinline__ uint32_t smem_u32(const void* p) {
    uint32_t a;
    asm("{ .reg .u64 t; cvta.to.shared.u64 t, %1; cvt.u32.u64 %0, t; }"
        : "=r"(a) : "l"(p));
    return a;
}
__device__ __forceinline__ void cp16(uint32_t dst, const void* src) {
    asm volatile("cp.async.cg.shared.global [%0], [%1], 16;" :: "r"(dst), "l"(src));
}
#define CP_COMMIT() asm volatile("cp.async.commit_group;" ::: "memory")
#define CP_WAIT(n)  asm volatile("cp.async.wait_group %0;" :: "n"(n) : "memory")
#define LDSM4(d, addr)                                                        \
    asm volatile("ldmatrix.sync.aligned.m8n8.x4.shared.b16 {%0,%1,%2,%3}, [%4];" \
                 : "=r"((d)[0]), "=r"((d)[1]), "=r"((d)[2]), "=r"((d)[3])     \
                 : "r"(addr))
#define LDSM4T(d, addr)                                                       \
    asm volatile("ldmatrix.sync.aligned.m8n8.x4.trans.shared.b16 {%0,%1,%2,%3}, [%4];" \
                 : "=r"((d)[0]), "=r"((d)[1]), "=r"((d)[2]), "=r"((d)[3])     \
                 : "r"(addr))
__device__ __forceinline__ void mma16816(float* c, const uint32_t* a,
                                         const uint32_t* b) {
    asm volatile(
        "mma.sync.aligned.m16n8k16.row.col.f32.bf16.bf16.f32 "
        "{%0,%1,%2,%3}, {%4,%5,%6,%7}, {%8,%9}, {%0,%1,%2,%3};"
        : "+f"(c[0]), "+f"(c[1]), "+f"(c[2]), "+f"(c[3])
        : "r"(a[0]), "r"(a[1]), "r"(a[2]), "r"(a[3]), "r"(b[0]), "r"(b[1]));
}
__device__ __forceinline__ void mma16816h(float* c, const uint32_t* a,
                                          const uint32_t* b) {
    asm volatile(
        "mma.sync.aligned.m16n8k16.row.col.f32.f16.f16.f32 "
        "{%0,%1,%2,%3}, {%4,%5,%6,%7}, {%8,%9}, {%0,%1,%2,%3};"
        : "+f"(c[0]), "+f"(c[1]), "+f"(c[2]), "+f"(c[3])
        : "r"(a[0]), "r"(a[1]), "r"(a[2]), "r"(a[3]), "r"(b[0]), "r"(b[1]));
}

// ---------------------------------------------------------------------------
// Scratch (device globals)
// ---------------------------------------------------------------------------
__device__ __align__(256) float g_qkv[cB * cS * 3 * cE];          // 402 MB
__device__ __align__(256) __nv_bfloat16 g_xnh[cB * cS * cE];
__device__ __align__(256) __nv_bfloat16 g_xnl[cB * cS * cE];
__device__ __align__(256) __nv_bfloat16 g_qwh[3 * cE * cE];
__device__ __align__(256) __nv_bfloat16 g_qwl[3 * cE * cE];
__device__ __align__(256) __nv_bfloat16 g_owh[cE * cE];
__device__ __align__(256) __nv_bfloat16 g_owl[cE * cE];
__device__ __align__(256) __nv_bfloat16 g_ah[cB * cS * cE];
__device__ __align__(256) __nv_bfloat16 g_al[cB * cS * cE];
// Attention operands: layout [b][h][s][d]
__device__ __align__(256) __nv_bfloat16 g_qh[cB * cH * cS * HDIM];
__device__ __align__(256) __nv_bfloat16 g_ql[cB * cH * cS * HDIM];
__device__ __align__(256) __nv_bfloat16 g_kh[cB * cH * cS * HDIM];
__device__ __align__(256) __nv_bfloat16 g_kl[cB * cH * cS * HDIM];
__device__ __align__(256) __half       g_vf[cB * cH * cS * HDIM];
__device__ float g_cos[cS * (HDIM / 2)];
__device__ float g_sin[cS * (HDIM / 2)];

__device__ __forceinline__ uint32_t pack_bf2(float a, float b) {
    __nv_bfloat162 t;
    t.x = __float2bfloat16_rn(a);
    t.y = __float2bfloat16_rn(b);
    return *(uint32_t*)&t;
}

// ---------------------------------------------------------------------------
// LayerNorm -> bf16 hi/lo split output
// ---------------------------------------------------------------------------
__global__ __launch_bounds__(256) void ln_split_kernel(const float* __restrict__ x,
                                                       const float* __restrict__ w,
                                                       const float* __restrict__ b) {
    int row = blockIdx.x;
    int t = threadIdx.x;
    const float4* xr = (const float4*)(x + (size_t)row * cE);

    float4 v0 = xr[t];
    float4 v1 = xr[t + 256];

    float s = v0.x + v0.y + v0.z + v0.w + v1.x + v1.y + v1.z + v1.w;
    float ss = v0.x * v0.x + v0.y * v0.y + v0.z * v0.z + v0.w * v0.w +
               v1.x * v1.x + v1.y * v1.y + v1.z * v1.z + v1.w * v1.w;

    for (int off = 16; off; off >>= 1) {
        s  += __shfl_down_sync(0xffffffffu, s, off);
        ss += __shfl_down_sync(0xffffffffu, ss, off);
    }
    __shared__ float red0[8], red1[8];
    int warp = t >> 5, lane = t & 31;
    if (lane == 0) { red0[warp] = s; red1[warp] = ss; }
    __syncthreads();
    __shared__ float sMean, sRstd;
    if (t == 0) {
        float ts = 0.f, tss = 0.f;
        for (int i = 0; i < 8; i++) { ts += red0[i]; tss += red1[i]; }
        float mean = ts * (1.f / cE);
        float var = tss * (1.f / cE) - mean * mean;
        sMean = mean;
        sRstd = rsqrtf(var + 1e-5f);
    }
    __syncthreads();
    float mean = sMean, rstd = sRstd;

    const float4* wr = (const float4*)w;
    const float4* br = (const float4*)b;
    uint2* hr = (uint2*)(g_xnh + (size_t)row * cE);
    uint2* lr = (uint2*)(g_xnl + (size_t)row * cE);

#pragma unroll
    for (int half = 0; half < 2; half++) {
        int idx = t + half * 256;
        float4 v = half ? v1 : v0;
        float4 wv = wr[idx], bv = br[idx];
        float o0 = (v.x - mean) * rstd * wv.x + bv.x;
        float o1 = (v.y - mean) * rstd * wv.y + bv.y;
        float o2 = (v.z - mean) * rstd * wv.z + bv.z;
        float o3 = (v.w - mean) * rstd * wv.w + bv.w;
        __nv_bfloat16 h0 = __float2bfloat16_rn(o0);
        __nv_bfloat16 h1 = __float2bfloat16_rn(o1);
        __nv_bfloat16 h2 = __float2bfloat16_rn(o2);
        __nv_bfloat16 h3 = __float2bfloat16_rn(o3);
        uint2 hv, lv;
        {
            __nv_bfloat162 p01; p01.x = h0; p01.y = h1;
            __nv_bfloat162 p23; p23.x = h2; p23.y = h3;
            hv.x = *(uint32_t*)&p01; hv.y = *(uint32_t*)&p23;
        }
        lv.x = pack_bf2(o0 - __bfloat162float(h0), o1 - __bfloat162float(h1));
        lv.y = pack_bf2(o2 - __bfloat162float(h2), o3 - __bfloat162float(h3));
        hr[idx] = hv;
        lr[idx] = lv;
    }
}

// ---------------------------------------------------------------------------
// fp32 -> bf16 hi/lo split (weights)
// ---------------------------------------------------------------------------
__global__ __launch_bounds__(256) void split_kernel(const float* __restrict__ src,
                                                    __nv_bfloat16* __restrict__ hi,
                                                    __nv_bfloat16* __restrict__ lo,
                                                    int n4) {
    int i = blockIdx.x * 256 + threadIdx.x;
    if (i >= n4) return;
    float4 v = ((const float4*)src)[i];
    __nv_bfloat16 h0 = __float2bfloat16_rn(v.x);
    __nv_bfloat16 h1 = __float2bfloat16_rn(v.y);
    __nv_bfloat16 h2 = __float2bfloat16_rn(v.z);
    __nv_bfloat16 h3 = __float2bfloat16_rn(v.w);
    uint2 hv, lv;
    {
        __nv_bfloat162 p01; p01.x = h0; p01.y = h1;
        __nv_bfloat162 p23; p23.x = h2; p23.y = h3;
        hv.x = *(uint32_t*)&p01; hv.y = *(uint32_t*)&p23;
    }
    lv.x = pack_bf2(v.x - __bfloat162float(h0), v.y - __bfloat162float(h1));
    lv.y = pack_bf2(v.z - __bfloat162float(h2), v.w - __bfloat162float(h3));
    ((uint2*)hi)[i] = hv;
    ((uint2*)lo)[i] = lv;
}

// ---------------------------------------------------------------------------
// RoPE angles
// ---------------------------------------------------------------------------
__global__ void ang_kernel(const float* __restrict__ freqs,
                           const float* __restrict__ pos) {
    int s = blockIdx.x;
    int f = threadIdx.x;  // 0..63
    float a = freqs[f * 3 + 0] * pos[s * 3 + 0] +
              freqs[f * 3 + 1] * pos[s * 3 + 1] +
              freqs[f * 3 + 2] * pos[s * 3 + 2];
    g_cos[s * 64 + f] = cosf(a);
    g_sin[s * 64 + f] = sinf(a);
}

// ---------------------------------------------------------------------------
// RoPE + transpose to [b][h][s][d] + bf16 hi/lo split. Scale folded into Q.
// ---------------------------------------------------------------------------
__global__ __launch_bounds__(256) void rope_split_kernel() {
    int gid = blockIdx.x * 256 + threadIdx.x;
    const int N = cB * cS * cH * 64;
    int part = (gid >= N) ? 1 : 0;
    int r = gid - part * N;
    int f = r & 63;
    int h = (r >> 6) & 15;
    int s = (r >> 10) & 4095;
    int b = r >> 22;
    float c = g_cos[s * 64 + f];
    float sn = g_sin[s * 64 + f];
    float2 t = *(const float2*)(g_qkv + ((size_t)(b * cS + s)) * (3 * cE) +
                                part * cE + h * HDIM + 2 * f);
    float ox = t.x * c - t.y * sn;
    float oy = t.x * sn + t.y * c;
    if (!part) {
        const float scale = 0.088388347648318440550f;  // 1/sqrt(128)
        ox *= scale; oy *= scale;
    }
    __nv_bfloat16 hx = __float2bfloat16_rn(ox);
    __nv_bfloat16 hy = __float2bfloat16_rn(oy);
    uint32_t hv;
    { __nv_bfloat162 p; p.x = hx; p.y = hy; hv = *(uint32_t*)&p; }
    uint32_t lv = pack_bf2(ox - __bfloat162float(hx), oy - __bfloat162float(hy));
    size_t o = (((size_t)(b * cH + h) * cS + s) * HDIM + 2 * f) >> 1;
    if (!part) {
        ((uint32_t*)g_qh)[o] = hv;
        ((uint32_t*)g_ql)[o] = lv;
    } else {
        ((uint32_t*)g_kh)[o] = hv;
        ((uint32_t*)g_kl)[o] = lv;
    }
}

// ---------------------------------------------------------------------------
// V -> fp16, transposed to [b][h][s][d]
// ---------------------------------------------------------------------------
__global__ __launch_bounds__(256) void vconv_kernel() {
    int gid = blockIdx.x * 256 + threadIdx.x;  // over B*S*E/2 pairs
    int d2 = gid & 63;
    int h = (gid >> 6) & 15;
    int s = (gid >> 10) & 4095;
    int b = gid >> 22;
    float2 v = *(const float2*)(g_qkv + ((size_t)(b * cS + s)) * (3 * cE) +
                                2 * cE + h * HDIM + 2 * d2);
    __half2 hv = __floats2half2_rn(v.x, v.y);
    *(__half2*)(g_vf + ((size_t)(b * cH + h) * cS + s) * HDIM + 2 * d2) = hv;
}

// ---------------------------------------------------------------------------
// HMMA bf16-split GEMM (unchanged from R3)
// ---------------------------------------------------------------------------
#define GBK 32
#define TSTRIDE 72
#define TROWB (TSTRIDE * 2)
#define TILE_B (128 * TROWB)
#define GEMM_SMEM (2 * 4 * TILE_B)

__global__ __launch_bounds__(256, 1) void gemm_bf3(
    const __nv_bfloat16* __restrict__ Ah, const __nv_bfloat16* __restrict__ Al,
    const __nv_bfloat16* __restrict__ Wh, const __nv_bfloat16* __restrict__ Wl,
    const float* __restrict__ bias, float* __restrict__ C, int N, int K) {
    extern __shared__ __align__(128) char smem[];
    uint32_t sb = smem_u32(smem);
    int tid = threadIdx.x;
    int wid = tid >> 5, lane = tid & 31;
    int bm = blockIdx.y * 128, bn = blockIdx.x * 128;
    int wm = wid & 1, wn = wid >> 1;

    const __nv_bfloat16* s0 = Ah + (size_t)bm * K;
    const __nv_bfloat16* s1 = Al + (size_t)bm * K;
    const __nv_bfloat16* s2 = Wh + (size_t)bn * K;
    const __nv_bfloat16* s3 = Wl + (size_t)bn * K;

    auto load = [&](int buf, int k0) {
        uint32_t base = sb + (uint32_t)buf * (4 * TILE_B);
#pragma unroll
        for (int i = 0; i < 2; i++) {
            int idx = tid + i * 256;
            int row = idx >> 2, c = idx & 3;
            uint32_t so = (uint32_t)row * TROWB + c * 16;
            size_t go = (size_t)row * K + k0 + c * 8;
            cp16(base + 0 * TILE_B + so, s0 + go);
            cp16(base + 1 * TILE_B + so, s1 + go);
            cp16(base + 2 * TILE_B + so, s2 + go);
            cp16(base + 3 * TILE_B + so, s3 + go);
        }
        CP_COMMIT();
    };

    float acc[4][4][4];
#pragma unroll
    for (int mf = 0; mf < 4; mf++)
#pragma unroll
        for (int nf = 0; nf < 4; nf++)
#pragma unroll
            for (int e = 0; e < 4; e++) acc[mf][nf][e] = 0.f;

    int g = lane >> 3, r = lane & 7;
    uint32_t a_row = (uint32_t)(r + (g & 1) * 8) * TROWB + (uint32_t)(g >> 1) * 16;
    uint32_t b_row = (uint32_t)(r + (g >> 1) * 8) * TROWB + (uint32_t)(g & 1) * 16;

    load(0, 0);
    int nCh = K / GBK;
    for (int ic = 0; ic < nCh; ic++) {
        int buf = ic & 1;
        if (ic + 1 < nCh) {
            load(buf ^ 1, (ic + 1) * GBK);
            CP_WAIT(1);
        } else {
            CP_WAIT(0);
        }
        __syncthreads();

        uint32_t base = sb + (uint32_t)buf * (4 * TILE_B);
        uint32_t aH = base + 0 * TILE_B + (uint32_t)(wm * 64) * TROWB + a_row;
        uint32_t aL = base + 1 * TILE_B + (uint32_t)(wm * 64) * TROWB + a_row;
        uint32_t bH = base + 2 * TILE_B + (uint32_t)(wn * 32) * TROWB + b_row;
        uint32_t bL = base + 3 * TILE_B + (uint32_t)(wn * 32) * TROWB + b_row;

#pragma unroll
        for (int kk = 0; kk < GBK; kk += 16) {
            uint32_t ah[4][4], al[4][4];
#pragma unroll
            for (int mf = 0; mf < 4; mf++) {
                LDSM4(ah[mf], aH + (uint32_t)(mf * 16) * TROWB + kk * 2);
                LDSM4(al[mf], aL + (uint32_t)(mf * 16) * TROWB + kk * 2);
            }
            uint32_t bh[2][4], bl[2][4];
#pragma unroll
            for (int nb = 0; nb < 2; nb++) {
                LDSM4(bh[nb], bH + (uint32_t)(nb * 16) * TROWB + kk * 2);
                LDSM4(bl[nb], bL + (uint32_t)(nb * 16) * TROWB + kk * 2);
            }
#pragma unroll
            for (int mf = 0; mf < 4; mf++) {
#pragma unroll
                for (int nf = 0; nf < 4; nf++) {
                    uint32_t* ph = &bh[nf >> 1][(nf & 1) * 2];
                    uint32_t* pl = &bl[nf >> 1][(nf & 1) * 2];
                    mma16816(acc[mf][nf], ah[mf], ph);
                    mma16816(acc[mf][nf], ah[mf], pl);
                    mma16816(acc[mf][nf], al[mf], ph);
                }
            }
        }
        __syncthreads();
    }

    int gq = lane >> 2, tc = lane & 3;
#pragma unroll
    for (int mf = 0; mf < 4; mf++) {
        int row0 = bm + wm * 64 + mf * 16 + gq;
#pragma unroll
        for (int nf = 0; nf < 4; nf++) {
            int col = bn + wn * 32 + nf * 8 + tc * 2;
            float b0 = bias[col], b1 = bias[col + 1];
            float2 v0, v1;
            v0.x = acc[mf][nf][0] + b0;
            v0.y = acc[mf][nf][1] + b1;
            v1.x = acc[mf][nf][2] + b0;
            v1.y = acc[mf][nf][3] + b1;
            *(float2*)(C + (size_t)row0 * N + col) = v0;
            *(float2*)(C + (size_t)(row0 + 8) * N + col) = v1;
        }
    }
}

// ---------------------------------------------------------------------------
// HMMA flash attention: 128 q rows x 64 kv tile, 8 warps (16 rows each).
// QK^T: bf16 hi/lo 3-MMA. Softmax in registers. PV: fp16 single.
// Output written directly as bf16 hi/lo (g_ah/g_al) in [b][s][h*128+d].
// ---------------------------------------------------------------------------
#define FROWB 272                       // 128 elems * 2B + 16 pad
#define FQ_H 0u
#define FQ_L 34816u
#define FKV0 69632u
#define FKVSTRIDE 52224u                // Kh + Kl + V (3 * 17408)
#define FKH 0u
#define FKL 17408u
#define FV  34816u
#define FLASH_SMEM 174080

__global__ __launch_bounds__(256, 1) void flash_hmma() {
    extern __shared__ __align__(128) char smem[];
    uint32_t sb = smem_u32(smem);
    int tid = threadIdx.x;
    int wid = tid >> 5, lane = tid & 31;
    int gq = lane >> 2, tc = lane & 3;
    int g = lane >> 3, r = lane & 7;
    int qt = blockIdx.x;
    int bh = blockIdx.y;

    size_t qoff = ((size_t)bh * cS + qt * 128) * HDIM;
    const __nv_bfloat16* pqh = g_qh + qoff;
    const __nv_bfloat16* pql = g_ql + qoff;
    size_t kvbase = (size_t)bh * cS * HDIM;

    // Load Q (hi+lo) to smem
#pragma unroll
    for (int i = 0; i < 8; i++) {
        int idx = tid + i * 256;          // 0..2047
        int row = idx >> 4, seg = idx & 15;
        uint32_t so = (uint32_t)row * FROWB + seg * 16;
        size_t go = (size_t)row * HDIM + seg * 8;
        cp16(sb + FQ_H + so, pqh + go);
        cp16(sb + FQ_L + so, pql + go);
    }
    CP_COMMIT();

    auto loadKV = [&](int buf, int kt) {
        uint32_t base = sb + FKV0 + (uint32_t)buf * FKVSTRIDE;
#pragma unroll
        for (int i = 0; i < 4; i++) {
            int idx = tid + i * 256;      // 0..1023
            int row = idx >> 4, seg = idx & 15;
            uint32_t so = (uint32_t)row * FROWB + seg * 16;
            size_t go = kvbase + (size_t)(kt * 64 + row) * HDIM + seg * 8;
            cp16(base + FKH + so, g_kh + go);
            cp16(base + FKL + so, g_kl + go);
            cp16(base + FV + so, g_vf + go);
        }
        CP_COMMIT();
    };

    loadKV(0, 0);
    CP_WAIT(1);   // Q done
    __syncthreads();

    // Q fragments register-resident for whole kernel
    uint32_t qfh[8][4], qfl[8][4];
    {
        uint32_t a_addr = (uint32_t)(wid * 16 + r + (g & 1) * 8) * FROWB +
                          (uint32_t)(g >> 1) * 16;
#pragma unroll
        for (int kf = 0; kf < 8; kf++) {
            LDSM4(qfh[kf], sb + FQ_H + a_addr + kf * 32);
            LDSM4(qfl[kf], sb + FQ_L + a_addr + kf * 32);
        }
    }

    float m0 = -INFINITY, m1 = -INFINITY, l0 = 0.f, l1 = 0.f;
    float O[16][4];
#pragma unroll
    for (int nf = 0; nf < 16; nf++)
#pragma unroll
        for (int e = 0; e < 4; e++) O[nf][e] = 0.f;

    uint32_t kb_lane = (uint32_t)(r + (g >> 1) * 8) * FROWB + (uint32_t)(g & 1) * 16;
    uint32_t v_lane = (uint32_t)((g & 1) * 8 + r) * FROWB + (uint32_t)(g >> 1) * 16;

    const int nTiles = cS / 64;
    for (int kt = 0; kt < nTiles; kt++) {
        int buf = kt & 1;
        if (kt + 1 < nTiles) {
            loadKV(buf ^ 1, kt + 1);
            CP_WAIT(1);
        } else {
            CP_WAIT(0);
        }
        __syncthreads();

        uint32_t base = sb + FKV0 + (uint32_t)buf * FKVSTRIDE;

        // S = Q K^T (bf16 3-MMA split)
        float S[8][4];
#pragma unroll
        for (int nf = 0; nf < 8; nf++)
#pragma unroll
            for (int e = 0; e < 4; e++) S[nf][e] = 0.f;

#pragma unroll
        for (int nf16 = 0; nf16 < 4; nf16++) {
            uint32_t krow = base + (uint32_t)(nf16 * 16) * FROWB + kb_lane;
#pragma unroll
            for (int kf = 0; kf < 8; kf++) {
                uint32_t bh4[4], bl4[4];
                LDSM4(bh4, krow + FKH + kf * 32);
                LDSM4(bl4, krow + FKL + kf * 32);
                mma16816(S[2 * nf16], qfh[kf], &bh4[0]);
                mma16816(S[2 * nf16], qfh[kf], &bl4[0]);
                mma16816(S[2 * nf16], qfl[kf], &bh4[0]);
                mma16816(S[2 * nf16 + 1], qfh[kf], &bh4[2]);
                mma16816(S[2 * nf16 + 1], qfh[kf], &bl4[2]);
                mma16816(S[2 * nf16 + 1], qfl[kf], &bh4[2]);
            }
        }

        // Online softmax (rows gq / gq+8, stats replicated over 4 lanes)
        float mt0 = -INFINITY, mt1 = -INFINITY;
#pragma unroll
        for (int nf = 0; nf < 8; nf++) {
            mt0 = fmaxf(mt0, fmaxf(S[nf][0], S[nf][1]));
            mt1 = fmaxf(mt1, fmaxf(S[nf][2], S[nf][3]));
        }
        mt0 = fmaxf(mt0, __shfl_xor_sync(0xffffffffu, mt0, 1));
        mt0 = fmaxf(mt0, __shfl_xor_sync(0xffffffffu, mt0, 2));
        mt1 = fmaxf(mt1, __shfl_xor_sync(0xffffffffu, mt1, 1));
        mt1 = fmaxf(mt1, __shfl_xor_sync(0xffffffffu, mt1, 2));
        float mn0 = fmaxf(m0, mt0), mn1 = fmaxf(m1, mt1);
        float al0 = __expf(m0 - mn0), al1 = __expf(m1 - mn1);
        m0 = mn0; m1 = mn1;

        float rs0 = 0.f, rs1 = 0.f;
#pragma unroll
        for (int nf = 0; nf < 8; nf++) {
            S[nf][0] = __expf(S[nf][0] - m0);
            S[nf][1] = __expf(S[nf][1] - m0);
            S[nf][2] = __expf(S[nf][2] - m1);
            S[nf][3] = __expf(S[nf][3] - m1);
            rs0 += S[nf][0] + S[nf][1];
            rs1 += S[nf][2] + S[nf][3];
        }
        rs0 += __shfl_xor_sync(0xffffffffu, rs0, 1);
        rs0 += __shfl_xor_sync(0xffffffffu, rs0, 2);
        rs1 += __shfl_xor_sync(0xffffffffu, rs1, 1);
        rs1 += __shfl_xor_sync(0xffffffffu, rs1, 2);
        l0 = l0 * al0 + rs0;
        l1 = l1 * al1 + rs1;

        // Pack P to fp16 A-fragments
        uint32_t pa[4][4];
#pragma unroll
        for (int kb = 0; kb < 4; kb++) {
            __half2 t0 = __floats2half2_rn(S[2 * kb][0], S[2 * kb][1]);
            __half2 t1 = __floats2half2_rn(S[2 * kb][2], S[2 * kb][3]);
            __half2 t2 = __floats2half2_rn(S[2 * kb + 1][0], S[2 * kb + 1][1]);
            __half2 t3 = __floats2half2_rn(S[2 * kb + 1][2], S[2 * kb + 1][3]);
            pa[kb][0] = *(uint32_t*)&t0;
            pa[kb][1] = *(uint32_t*)&t1;
            pa[kb][2] = *(uint32_t*)&t2;
            pa[kb][3] = *(uint32_t*)&t3;
        }

        // Rescale O
#pragma unroll
        for (int nf = 0; nf < 16; nf++) {
            O[nf][0] *= al0; O[nf][1] *= al0;
            O[nf][2] *= al1; O[nf][3] *= al1;
        }

        // O += P V (fp16)
        uint32_t vb0 = base + FV + v_lane;
#pragma unroll
        for (int nf16 = 0; nf16 < 8; nf16++) {
#pragma unroll
            for (int kb = 0; kb < 4; kb++) {
                uint32_t vb[4];
                LDSM4T(vb, vb0 + (uint32_t)(kb * 16) * FROWB + nf16 * 32);
                mma16816h(O[2 * nf16], pa[kb], &vb[0]);
                mma16816h(O[2 * nf16 + 1], pa[kb], &vb[2]);
            }
        }
        __syncthreads();
    }

    // Epilogue: normalize, split to bf16 hi/lo, write g_ah/g_al
    float linv0 = 1.f / l0, linv1 = 1.f / l1;
    int b = bh >> 4, h = bh & 15;
    size_t row0 = (size_t)b * cS + qt * 128 + wid * 16 + gq;
    size_t row1 = row0 + 8;
    uint32_t* ah0 = (uint32_t*)(g_ah + row0 * cE + h * HDIM);
    uint32_t* al_0 = (uint32_t*)(g_al + row0 * cE + h * HDIM);
    uint32_t* ah1 = (uint32_t*)(g_ah + row1 * cE + h * HDIM);
    uint32_t* al_1 = (uint32_t*)(g_al + row1 * cE + h * HDIM);
#pragma unroll
    for (int nf = 0; nf < 16; nf++) {
        int cw = (nf * 8 + tc * 2) >> 1;  // uint32 index
        float v0 = O[nf][0] * linv0, v1 = O[nf][1] * linv0;
        float v2 = O[nf][2] * linv1, v3 = O[nf][3] * linv1;
        __nv_bfloat16 h0 = __float2bfloat16_rn(v0);
        __nv_bfloat16 h1 = __float2bfloat16_rn(v1);
        __nv_bfloat16 h2 = __float2bfloat16_rn(v2);
        __nv_bfloat16 h3 = __float2bfloat16_rn(v3);
        uint32_t hv0, hv1;
        { __nv_bfloat162 p; p.x = h0; p.y = h1; hv0 = *(uint32_t*)&p; }
        { __nv_bfloat162 p; p.x = h2; p.y = h3; hv1 = *(uint32_t*)&p; }
        ah0[cw] = hv0;
        al_0[cw] = pack_bf2(v0 - __bfloat162float(h0), v1 - __bfloat162float(h1));
        ah1[cw] = hv1;
        al_1[cw] = pack_bf2(v2 - __bfloat162float(h2), v3 - __bfloat162float(h3));
    }
}

// ---------------------------------------------------------------------------
// Launch
// ---------------------------------------------------------------------------
extern "C" void kernel_launch(void* const* d_in, const int* in_sizes, int n_in,
                              void* d_out, int out_size) {
    const float* x        = (const float*)d_in[0];
    const float* position = (const float*)d_in[1];
    const float* ln_w     = (const float*)d_in[2];
    const float* ln_b     = (const float*)d_in[3];
    const float* qkv_w    = (const float*)d_in[4];
    const float* qkv_b    = (const float*)d_in[5];
    const float* out_w    = (const float*)d_in[6];
    const float* out_b    = (const float*)d_in[7];
    const float* freqs    = (const float*)d_in[8];
    float* out = (float*)d_out;

    float* pqkv;
    __nv_bfloat16 *pxnh, *pxnl, *pqwh, *pqwl, *powh, *powl, *pah, *pal;
    cudaGetSymbolAddress((void**)&pqkv, g_qkv);
    cudaGetSymbolAddress((void**)&pxnh, g_xnh);
    cudaGetSymbolAddress((void**)&pxnl, g_xnl);
    cudaGetSymbolAddress((void**)&pqwh, g_qwh);
    cudaGetSymbolAddress((void**)&pqwl, g_qwl);
    cudaGetSymbolAddress((void**)&powh, g_owh);
    cudaGetSymbolAddress((void**)&powl, g_owl);
    cudaGetSymbolAddress((void**)&pah, g_ah);
    cudaGetSymbolAddress((void**)&pal, g_al);

    cudaFuncSetAttribute(gemm_bf3, cudaFuncAttributeMaxDynamicSharedMemorySize,
                         GEMM_SMEM);
    cudaFuncSetAttribute(flash_hmma, cudaFuncAttributeMaxDynamicSharedMemorySize,
                         FLASH_SMEM);

    // 1. LayerNorm -> bf16 hi/lo
    ln_split_kernel<<<cB * cS, 256>>>(x, ln_w, ln_b);

    // 2. RoPE angle tables
    ang_kernel<<<cS, 64>>>(freqs, position);

    // 3. Split QKV weights
    split_kernel<<<(3 * cE * cE / 4 + 255) / 256, 256>>>(qkv_w, pqwh, pqwl,
                                                         3 * cE * cE / 4);

    // 4. QKV projection (HMMA)
    gemm_bf3<<<dim3(3 * cE / 128, cB * cS / 128), 256, GEMM_SMEM>>>(
        pxnh, pxnl, pqwh, pqwl, qkv_b, pqkv, 3 * cE, cE);

    // 5. RoPE + transpose + split q,k ; convert v -> fp16
    rope_split_kernel<<<(2 * cB * cS * cH * 64) / 256, 256>>>();
    vconv_kernel<<<(cB * cS * cE / 2) / 256, 256>>>();

    // 6. Flash attention (HMMA)
    flash_hmma<<<dim3(cS / 128, cB * cH), 256, FLASH_SMEM>>>();

    // 7. Split out weights
    split_kernel<<<(cE * cE / 4 + 255) / 256, 256>>>(out_w, powh, powl,
                                                     cE * cE / 4);

    // 8. Output projection (HMMA) -> d_out
    gemm_bf3<<<dim3(cE / 128, cB * cS / 128), 256, GEMM_SMEM>>>(
        pah, pal, powh, powl, out_b, out, cE, cE);
}